// round 10
// baseline (speedup 1.0000x reference)
#include <cuda_runtime.h>
#include <cuda_bf16.h>

// Upscale_15358803050749: upfirdn2d up=2, 4x4 kernel [1,3,3,1]^2, gain 4.
// x: (8,128,128,128) f32 -> out: (8,128,256,256) f32.
//
// Polyphase (reference's dilated conv, pad0=2), separably factored:
//   K[v][u] = C[v]*D[u],  D[u]=K[0][u],  C[v]=K[v][0]/K[0][0]  (C0==1)
//   horiz: out col 2i   = D3*x[i-1] + D1*x[i]
//          out col 2i+1 = D2*x[i]   + D0*x[i+1]
//   vert : out row 2r   = C3*row(r-1) + C1*row(r)
//          out row 2r+1 = C2*row(r)   + row(r+1)
//
// R10 = R9 scaled to 4 input rows/thread (8 output rows):
//   - 6 LDG.128 (rows iy0-1 .. iy0+4), vertical read amp 2.0 -> 1.5
//   - intra-warp smem exchange of the 6 raw rows (STS/LDS.128, lane+1 wrap)
//   - lane 31's neighbor wraps to lane 0 (= x[0..3]); its outputs wrap to
//     out cols [0..3], requiring exactly 2 masked terms per out row
//   - out rows computed+stored one at a time to bound live registers

#define W_IN   128
#define H_IN   128
#define W_OUT  256
#define NC     1024          // 8 * 128 planes
#define QRP    32            // thread-rows per plane (4 input rows each)

__global__ __launch_bounds__(128, 8)
void Upscale_15358803050749_kernel(const float* __restrict__ x,
                                   const float* __restrict__ k,
                                   float* __restrict__ out) {
    __shared__ float4 sm[4 * 6 * 32];     // 4 warps x 6 rows x 32 lanes = 12KB

    int t    = blockIdx.x * blockDim.x + threadIdx.x;
    int lane = t & 31;
    int wid  = (threadIdx.x >> 5) & 3;
    int rp   = t >> 5;
    int ry   = rp & (QRP - 1);
    int pl   = rp >> 5;                   // plane 0..NC-1  (QRP=32 -> shift 5)
    int iy0  = ry * 4;                    // first input row of this thread
    int ix0  = lane * 4;

    const float* xp = x   + pl * (H_IN * W_IN);
    float*       op = out + pl * (256 * W_OUT);

    // ---- 6 independent vector loads (rows iy0-1 .. iy0+4), MLP=6 ----
    bool vm = (iy0 > 0);
    bool ve = (iy0 + 4 < H_IN);
    const float* pr[6];
    pr[0] = xp + (vm ? (iy0 - 1) * W_IN : 0) + ix0;
    pr[1] = xp + (iy0    ) * W_IN + ix0;
    pr[2] = xp + (iy0 + 1) * W_IN + ix0;
    pr[3] = xp + (iy0 + 2) * W_IN + ix0;
    pr[4] = xp + (iy0 + 3) * W_IN + ix0;
    pr[5] = xp + (ve ? (iy0 + 4) * W_IN : 0) + ix0;

    float4 V[6];
    #pragma unroll
    for (int r = 0; r < 6; r++)
        V[r] = *reinterpret_cast<const float4*>(pr[r]);

    // ---- separable factors (overlaps load latency) ----
    float D0 = __ldg(k + 0), D1 = __ldg(k + 1), D2 = __ldg(k + 2), D3 = __ldg(k + 3);
    float inv = 1.0f / D0;
    float C1 = __ldg(k + 4)  * inv;
    float C2 = __ldg(k + 8)  * inv;
    float C3 = __ldg(k + 12) * inv;     // C0 == 1

    // ---- intra-warp halo exchange via smem (lane+1, wrap to lane 0) ----
    float4* wsm = sm + wid * (6 * 32);
    #pragma unroll
    for (int r = 0; r < 6; r++) wsm[r * 32 + lane] = V[r];
    __syncwarp();
    int ln = (lane + 1) & 31;
    float4 N[6];
    #pragma unroll
    for (int r = 0; r < 6; r++) N[r] = wsm[r * 32 + ln];

    // ---- per-row 6-value windows: x[4l+1..4l+6] (masked halo rows) ----
    float zm = vm ? 1.f : 0.f;
    float ze = ve ? 1.f : 0.f;
    float T[6][6];
    #pragma unroll
    for (int r = 0; r < 6; r++) {
        T[r][0] = V[r].y; T[r][1] = V[r].z; T[r][2] = V[r].w;
        T[r][3] = N[r].x; T[r][4] = N[r].y; T[r][5] = N[r].z;
    }
    #pragma unroll
    for (int j = 0; j < 6; j++) { T[0][j] *= zm; T[5][j] *= ze; }

    bool last = (lane == 31);            // wrap lane: mask x[128] terms
    int cA = 8 * lane + 4;               // out cols [8l+4..8l+7]
    int cB = (8 * lane + 8) & (W_OUT - 1); // [8l+8..8l+11] (lane31 -> 0..3)
    float* q = op + (2 * iy0) * W_OUT;

    // ---- 8 output rows: vertical combine (6 FMA) -> horizontal -> store ----
    #pragma unroll
    for (int r = 0; r < 4; r++) {
        // even out row 2*(iy0+r):   C3*T[r] + C1*T[r+1]
        // odd  out row 2*(iy0+r)+1: C2*T[r+1] + T[r+2]
        float E[6], O[6];
        #pragma unroll
        for (int j = 0; j < 6; j++) {
            E[j] = C3 * T[r][j] + C1 * T[r + 1][j];
            O[j] = C2 * T[r + 1][j] + T[r + 2][j];
        }
        #pragma unroll
        for (int s = 0; s < 2; s++) {
            const float* Trow = s ? O : E;
            float w2z = last ? 0.f : Trow[2];
            float x3z = last ? 0.f : Trow[3];
            float o0 = D3*Trow[0] + D1*Trow[1];
            float o1 = D2*Trow[1] + D0*Trow[2];
            float o2 = D3*Trow[1] + D1*Trow[2];
            float o3 = D2*Trow[2] + D0*x3z;
            float o4 = D3*w2z     + D1*Trow[3];
            float o5 = D2*Trow[3] + D0*Trow[4];
            float o6 = D3*Trow[3] + D1*Trow[4];
            float o7 = D2*Trow[4] + D0*Trow[5];
            float* qr = q + (2 * r + s) * W_OUT;
            __stcs(reinterpret_cast<float4*>(qr + cA), make_float4(o0, o1, o2, o3));
            __stcs(reinterpret_cast<float4*>(qr + cB), make_float4(o4, o5, o6, o7));
        }
    }
}

extern "C" void kernel_launch(void* const* d_in, const int* in_sizes, int n_in,
                              void* d_out, int out_size) {
    const float* x = (const float*)d_in[0];   // (8,128,128,128)
    const float* k = (const float*)d_in[1];   // (4,4)
    float* out = (float*)d_out;               // (8,128,256,256)

    // threads = NC * QRP * 32 = 1,048,576 ; blocks = 8192 @ 128 thr
    int threads = 128;
    int blocks = (NC * QRP * 32) / threads;
    Upscale_15358803050749_kernel<<<blocks, threads>>>(x, k, out);
}